// round 1
// baseline (speedup 1.0000x reference)
#include <cuda_runtime.h>
#include <cstddef>

#define BB 4
#define SS 1024
#define HIDD 1024
#define HH 16
#define DD 64

// scratch: q,k,v in [B,H,S,D] layout (16MB each)
__device__ float g_q[BB*HH*SS*DD];
__device__ float g_k[BB*HH*SS*DD];
__device__ float g_v[BB*HH*SS*DD];

// ---------------------------------------------------------------------------
// Fused QKV SGEMM: C = A @ W + b, A = hidden [4096,1024], W [1024,1024]
// grid: (M/64=64, 3*1024/64=48), block 256, each thread 4x4.
// Output written in [B,H,S,D] layout.
// ---------------------------------------------------------------------------
__global__ __launch_bounds__(256) void qkv_kernel(
    const float* __restrict__ A,
    const float* __restrict__ Wq, const float* __restrict__ bq,
    const float* __restrict__ Wk, const float* __restrict__ bk,
    const float* __restrict__ Wv, const float* __restrict__ bv)
{
    __shared__ float As[16][68];   // [k][m], padded for float4-aligned reads
    __shared__ float Ws[16][64];   // [k][n]

    int tid = threadIdx.x;
    int ty = tid >> 4, tx = tid & 15;
    int m0 = blockIdx.x * 64;
    int ng = blockIdx.y * 64;
    int sel = ng >> 10;            // 0=q,1=k,2=v
    int n0 = ng & 1023;

    const float* W    = (sel == 0) ? Wq : (sel == 1) ? Wk : Wv;
    const float* bias = (sel == 0) ? bq : (sel == 1) ? bk : bv;
    float* out        = (sel == 0) ? g_q : (sel == 1) ? g_k : g_v;

    float acc[4][4] = {};

    for (int k0 = 0; k0 < HIDD; k0 += 16) {
        #pragma unroll
        for (int p = 0; p < 4; p++) {
            int idx = tid + p * 256;
            int ml = idx >> 4, kk = idx & 15;
            As[kk][ml] = A[(m0 + ml) * HIDD + k0 + kk];
            int kk2 = idx >> 6, nn = idx & 63;
            Ws[kk2][nn] = W[(k0 + kk2) * HIDD + n0 + nn];
        }
        __syncthreads();
        #pragma unroll
        for (int kk = 0; kk < 16; kk++) {
            float4 a4 = *(const float4*)&As[kk][ty * 4];
            float4 w4 = *(const float4*)&Ws[kk][tx * 4];
            float a[4] = {a4.x, a4.y, a4.z, a4.w};
            float w[4] = {w4.x, w4.y, w4.z, w4.w};
            #pragma unroll
            for (int i = 0; i < 4; i++)
                #pragma unroll
                for (int j = 0; j < 4; j++)
                    acc[i][j] += a[i] * w[j];
        }
        __syncthreads();
    }

    // store with bias, heads layout [B,H,S,D]
    int nc0 = n0 + tx * 4;
    int h_ = nc0 >> 6;
    int d0 = nc0 & 63;
    float b0 = bias[nc0 + 0], b1 = bias[nc0 + 1], b2 = bias[nc0 + 2], b3 = bias[nc0 + 3];
    #pragma unroll
    for (int i = 0; i < 4; i++) {
        int mg = m0 + ty * 4 + i;
        int b_ = mg >> 10, s_ = mg & 1023;
        float4 o;
        o.x = acc[i][0] + b0;
        o.y = acc[i][1] + b1;
        o.z = acc[i][2] + b2;
        o.w = acc[i][3] + b3;
        *(float4*)&out[((b_ * HH + h_) * SS + s_) * DD + d0] = o;
    }
}

// ---------------------------------------------------------------------------
// Attention: one CTA = 64 query rows of one (b,h). Single streaming pass over
// 16 key tiles (reference softmax has no max subtraction):
//   s = q.(k + E[l-r+1023]); p = exp(s/8 + amask)*skim; acc += p@V; rsum += p
// grid (16, 16, 4) = (l-tile, h, b), block 256 (16x16 threads, 4x4 each).
// ---------------------------------------------------------------------------
#define PADQ 68
#define PADE 129
#define PADP 65

#define SM_QT   0
#define SM_KT   (SM_QT + 64 * PADQ)
#define SM_VS   (SM_KT + 64 * PADQ)
#define SM_ET   (SM_VS + 64 * 64)
#define SM_PS   (SM_ET + 64 * PADE)
#define SM_RED  (SM_PS + 64 * PADP)
#define SM_AM   (SM_RED + 64 * 16)
#define SM_SK   (SM_AM + 64)
#define SM_FLOATS (SM_SK + 64)
#define SM_BYTES (SM_FLOATS * 4)

__global__ __launch_bounds__(256) void attn_kernel(
    const float* __restrict__ amask,   // [B,1,1,S]
    const int*   __restrict__ skim,    // [B,S]
    const float* __restrict__ E,       // [2047, 64]
    float* __restrict__ out)           // [B,S,H,D]
{
    extern __shared__ float sm[];
    float* Qt  = sm + SM_QT;   // [d][l]
    float* Kt  = sm + SM_KT;   // [d][r]
    float* Vs  = sm + SM_VS;   // [r][d]
    float* Et  = sm + SM_ET;   // [d][jj], jj in [0,127), col 127 zero pad
    float* Ps  = sm + SM_PS;   // [l][r]
    float* red = sm + SM_RED;  // [l][tx]
    float* ams = sm + SM_AM;
    float* sks = sm + SM_SK;

    int tid = threadIdx.x;
    int ty = tid >> 4, tx = tid & 15;
    int b = blockIdx.z, h = blockIdx.y;
    int l0 = blockIdx.x * 64;
    int bh = b * HH + h;
    const float* qp = g_q + (size_t)bh * SS * DD;
    const float* kp = g_k + (size_t)bh * SS * DD;
    const float* vp = g_v + (size_t)bh * SS * DD;

    // load Q tile (transposed): Qt[d][l]
    #pragma unroll
    for (int p = 0; p < 16; p++) {
        int idx = tid + p * 256;
        int l = idx >> 6, d = idx & 63;
        Qt[d * PADQ + l] = qp[(l0 + l) * DD + d];
    }

    float acc[4][4] = {};
    float rsum[4] = {};
    int jjb = (ty - tx) * 4 + 63;   // jj for (i=0,j=0); needed e's are jjb-3..jjb+3

    for (int rt = 0; rt < 16; rt++) {
        int r0 = rt * 64;
        __syncthreads();   // prev-iteration PV reads done (also covers Q load for rt=0)

        #pragma unroll
        for (int p = 0; p < 16; p++) {
            int idx = tid + p * 256;
            int r = idx >> 6, d = idx & 63;
            Kt[d * PADQ + r] = kp[(r0 + r) * DD + d];
            Vs[r * 64 + d]   = vp[(r0 + r) * DD + d];
        }
        int jmin = l0 - r0 + 960;   // = l0 - (r0+63) + 1023, in [0, 1920]
        #pragma unroll
        for (int p = 0; p < 32; p++) {
            int idx = tid + p * 256;
            int jj = idx >> 6, d = idx & 63;
            Et[d * PADE + jj] = (jj < 127) ? E[(jmin + jj) * DD + d] : 0.0f;
        }
        if (tid < 64) {
            ams[tid] = amask[b * SS + r0 + tid];
            sks[tid] = (float)skim[b * SS + r0 + tid];
        }
        __syncthreads();

        // s[i][j] = sum_d q[l,d] * (k[r,d] + E[l-r+1023, d])
        float s[4][4] = {};
        #pragma unroll 4
        for (int d = 0; d < 64; d++) {
            float4 q4 = *(const float4*)&Qt[d * PADQ + ty * 4];
            float4 k4 = *(const float4*)&Kt[d * PADQ + tx * 4];
            float e[7];
            #pragma unroll
            for (int c = 0; c < 7; c++) e[c] = Et[d * PADE + jjb + c - 3];
            float q[4] = {q4.x, q4.y, q4.z, q4.w};
            float k[4] = {k4.x, k4.y, k4.z, k4.w};
            #pragma unroll
            for (int i = 0; i < 4; i++)
                #pragma unroll
                for (int j = 0; j < 4; j++)
                    s[i][j] += q[i] * (k[j] + e[i - j + 3]);
        }

        // masked exp, stash P, accumulate row sums
        #pragma unroll
        for (int j = 0; j < 4; j++) {
            int rl = tx * 4 + j;
            float am = ams[rl];
            float sk = sks[rl];
            #pragma unroll
            for (int i = 0; i < 4; i++) {
                float p = __expf(s[i][j] * 0.125f + am) * sk;
                rsum[i] += p;
                Ps[(ty * 4 + i) * PADP + rl] = p;
            }
        }
        __syncthreads();

        // acc += P @ V
        #pragma unroll 8
        for (int r = 0; r < 64; r++) {
            float4 v4 = *(const float4*)&Vs[r * 64 + tx * 4];
            float v[4] = {v4.x, v4.y, v4.z, v4.w};
            #pragma unroll
            for (int i = 0; i < 4; i++) {
                float p = Ps[(ty * 4 + i) * PADP + r];
                acc[i][0] += p * v[0];
                acc[i][1] += p * v[1];
                acc[i][2] += p * v[2];
                acc[i][3] += p * v[3];
            }
        }
    }

    // reduce row sums across the 16 column-threads
    __syncthreads();
    #pragma unroll
    for (int i = 0; i < 4; i++) red[(ty * 4 + i) * 16 + tx] = rsum[i];
    __syncthreads();

    #pragma unroll
    for (int i = 0; i < 4; i++) {
        float tot = 0.f;
        #pragma unroll
        for (int t = 0; t < 16; t++) tot += red[(ty * 4 + i) * 16 + t];
        float inv = 1.0f / (1e-8f + tot);
        int lg = l0 + ty * 4 + i;
        float4 o;
        o.x = acc[i][0] * inv;
        o.y = acc[i][1] * inv;
        o.z = acc[i][2] * inv;
        o.w = acc[i][3] * inv;
        *(float4*)&out[(((size_t)b * SS + lg) * HH + h) * DD + tx * 4] = o;
    }
}

extern "C" void kernel_launch(void* const* d_in, const int* in_sizes, int n_in,
                              void* d_out, int out_size)
{
    const float* hs    = (const float*)d_in[0];
    const float* amask = (const float*)d_in[1];
    const int*   skm   = (const int*)  d_in[2];
    const float* Wq    = (const float*)d_in[3];
    const float* bq    = (const float*)d_in[4];
    const float* Wk    = (const float*)d_in[5];
    const float* bk    = (const float*)d_in[6];
    const float* Wv    = (const float*)d_in[7];
    const float* bv    = (const float*)d_in[8];
    const float* E     = (const float*)d_in[9];
    float* out = (float*)d_out;

    cudaFuncSetAttribute(attn_kernel, cudaFuncAttributeMaxDynamicSharedMemorySize, SM_BYTES);

    qkv_kernel<<<dim3(64, 48), 256>>>(hs, Wq, bq, Wk, bk, Wv, bv);
    attn_kernel<<<dim3(16, 16, 4), 256, SM_BYTES>>>(amask, skm, E, out);
}